// round 12
// baseline (speedup 1.0000x reference)
#include <cuda_runtime.h>
#include <math.h>

#define Bc      8
#define Nc      1024
#define NTYPESc 2
#define MNc     128
#define Mc      256          // NTYPES*MN
#define BETAc   8
#define M1c     16
#define M2c     4
#define NFEATc  64           // M1*M2
#define Hc      128
#define NGHOSTc 64
#define NTOT    (Nc + NGHOSTc)   // 1088
#define RMAXc   6.0f
#define RMINc   0.5f
#define SPANc   5.5f
#define PI_F    3.14159265358979323846f

#define O_ETOT  0
#define O_EI    (O_ETOT + Bc)                 // 8
#define O_FORCE (O_EI + Bc*Nc)                // 8200
#define O_VIR   (O_FORCE + Bc*NTOT*3)         // 34312
#define OUT_TOTAL (O_VIR + Bc*9)              // 34384

typedef unsigned long long u64;

// ---------------- packed f32x2 helpers ----------------
__device__ __forceinline__ u64 pk2(float lo, float hi) {
    u64 r; asm("mov.b64 %0, {%1, %2};" : "=l"(r) : "f"(lo), "f"(hi)); return r;
}
__device__ __forceinline__ void upk2(u64 v, float& lo, float& hi) {
    asm("mov.b64 {%0, %1}, %2;" : "=f"(lo), "=f"(hi) : "l"(v));
}
__device__ __forceinline__ u64 ffma2(u64 a, u64 b, u64 c) {
    u64 d; asm("fma.rn.f32x2 %0, %1, %2, %3;" : "=l"(d) : "l"(a), "l"(b), "l"(c)); return d;
}

// fast tanh via MUFU: tanh(x) = 1 - 2/(exp(2x)+1)
// branchless; saturates correctly (exp->inf => 1, exp->0 => -1); ~1e-6 rel err
__device__ __forceinline__ float ftanh(float x) {
    float t = __expf(2.0f * x);
    return 1.0f - __fdividef(2.0f, t + 1.0f);
}

// ---------------- device scratch (no allocation allowed) ----------------
__device__ float  g_S    [Bc*Nc*NFEATc];   // S (B,N,16,4), already /M
__device__ float  g_feat [Bc*Nc*NFEATc];   // raw features
__device__ float  g_dfeat[Bc*Nc*NFEATc];   // dE/dfeat_raw (incl. 1/std)
__device__ double g_sum  [NTYPESc];
__device__ double g_sumsq[NTYPESc];
__device__ float  g_mu   [NTYPESc];
__device__ float  g_istd [NTYPESc];        // 1/std
__device__ float  g_W0T  [NTYPESc*Hc*NFEATc];  // [t][j][p]
__device__ float  g_W1T  [NTYPESc*Hc*Hc];      // [t][j][i]
__device__ float  g_W2T  [NTYPESc*Hc*Hc];

__device__ __forceinline__ float wsum(float v) {
    v += __shfl_xor_sync(0xffffffffu, v, 16);
    v += __shfl_xor_sync(0xffffffffu, v, 8);
    v += __shfl_xor_sync(0xffffffffu, v, 4);
    v += __shfl_xor_sync(0xffffffffu, v, 2);
    v += __shfl_xor_sync(0xffffffffu, v, 1);
    return v;
}

// packed butterfly step
template<int HALF, int OFF>
__device__ __forceinline__ void bstep(float* v, int lane) {
    bool hi = (lane & OFF) != 0;
#pragma unroll
    for (int i = 0; i < HALF; i++) {
        float send = hi ? v[i] : v[i + HALF];
        float recv = __shfl_xor_sync(0xffffffffu, send, OFF);
        v[i] = (hi ? v[i + HALF] : v[i]) + recv;
    }
}

// ---------------- kernel 0: zero outputs + transpose weights -------------
__global__ void prep_kernel(float* out,
                            const float* __restrict__ W0,
                            const float* __restrict__ W1,
                            const float* __restrict__ W2) {
    int i = blockIdx.x * blockDim.x + threadIdx.x;
    if (i < OUT_TOTAL) out[i] = 0.0f;
    if (i < NTYPESc) { g_sum[i] = 0.0; g_sumsq[i] = 0.0; }
    if (i < NTYPESc*Hc*NFEATc) {
        int t = i / (Hc*NFEATc); int r = i % (Hc*NFEATc);
        int j = r / NFEATc;      int p = r % NFEATc;
        g_W0T[i] = W0[(t*NFEATc + p)*Hc + j];
    }
    if (i < NTYPESc*Hc*Hc) {
        int t = i / (Hc*Hc); int r = i % (Hc*Hc);
        int j = r / Hc;      int k = r % Hc;
        g_W1T[i] = W1[(t*Hc + k)*Hc + j];
        g_W2T[i] = W2[(t*Hc + k)*Hc + j];
    }
}

// ---------------- kernel 2: features + per-type stats (round-8 exact) ----
__global__ void feat_kernel(const float* __restrict__ rvec,
                            const int*   __restrict__ tmap,
                            const float* __restrict__ cparam) {
    int bn = blockIdx.x;
    int n  = bn & (Nc - 1);
    int m  = threadIdx.x;
    int ti = tmap[n];

    __shared__ __align__(16) float ct[NTYPESc*BETAc*M1c];  // [tj][k][p]
    __shared__ float S_sh[NFEATc];
    __shared__ float Sn[NFEATc];
    __shared__ float ps[8], ps2[8];

    {   // load c transposed: source index m = tj*128 + p*8 + k
        int tjl = m >> 7, rem = m & 127, p = rem >> 3, k = rem & 7;
        ct[tjl*128 + k*16 + p] = cparam[ti * (NTYPESc*M1c*BETAc) + m];
    }
    if (m < NFEATc) S_sh[m] = 0.0f;
    __syncthreads();

    const float* rv = rvec + ((long)bn * Mc + m) * 3;
    float x = rv[0], y = rv[1], z = rv[2];
    float r2 = x*x + y*y + z*z;
    bool  valid = r2 > 1e-12f;
    float rinv0 = rsqrtf(fmaxf(r2, 1e-30f));
    float rs  = valid ? r2 * rinv0 : 1.0f;
    float inv = valid ? rinv0 : 1.0f;
    float u = 2.0f*(rs - RMINc)/SPANc - 1.0f;
    u = fminf(fmaxf(u, -1.0f), 1.0f);
    float rc = fminf(fmaxf(rs, RMINc), RMAXc);
    float fc = (valid && rs < RMAXc)
             ? 0.5f*(__cosf(PI_F*(rc - RMINc)/SPANc) + 1.0f) : 0.0f;

    float T[BETAc];
    T[0] = 1.0f; T[1] = u;
#pragma unroll
    for (int k = 2; k < BETAc; k++) T[k] = 2.0f*u*T[k-1] - T[k-2];
    u64 Td[BETAc];
#pragma unroll
    for (int k = 0; k < BETAc; k++) Td[k] = pk2(T[k], T[k]);

    int tj = m >> 7;
    const u64* cp = (const u64*)(ct + tj * 128);
    float q0 = valid ? 1.0f : 0.0f;
    float qv[4]; qv[0] = q0; qv[1] = x*inv*q0; qv[2] = y*inv*q0; qv[3] = z*inv*q0;

    u64 P2[8];
#pragma unroll
    for (int pp = 0; pp < 8; pp++) P2[pp] = 0ULL;
#pragma unroll
    for (int k = 0; k < BETAc; k++)
#pragma unroll
        for (int pp = 0; pp < 8; pp++) P2[pp] = ffma2(cp[k*8 + pp], Td[k], P2[pp]);

    float gv[M1c];
#pragma unroll
    for (int pp = 0; pp < 8; pp++) {
        float a, b; upk2(P2[pp], a, b);
        gv[2*pp + 0] = a * fc;
        gv[2*pp + 1] = b * fc;
    }

    float v[NFEATc];
#pragma unroll
    for (int p = 0; p < M1c; p++) {
        v[p*4 + 0] = gv[p] * qv[0];
        v[p*4 + 1] = gv[p] * qv[1];
        v[p*4 + 2] = gv[p] * qv[2];
        v[p*4 + 3] = gv[p] * qv[3];
    }
    int lane = m & 31;
    bstep<32, 16>(v, lane);
    bstep<16,  8>(v, lane);
    bstep< 8,  4>(v, lane);
    bstep< 4,  2>(v, lane);
    bstep< 2,  1>(v, lane);
    atomicAdd(&S_sh[2*lane + 0], v[0]);
    atomicAdd(&S_sh[2*lane + 1], v[1]);
    __syncthreads();

    if (m < NFEATc) {
        float s = S_sh[m] * (1.0f / Mc);
        Sn[m] = s;
        g_S[(long)bn * NFEATc + m] = s;
    }
    __syncthreads();

    float f = 0.0f;
    if (m < NFEATc) {
        int p = m >> 2, qi = m & 3;
#pragma unroll
        for (int a = 0; a < 4; a++) f += Sn[p*4 + a] * Sn[qi*4 + a];
        g_feat[(long)bn * NFEATc + m] = f;
    }
    float fs  = wsum(f);
    float f2s = wsum(f * f);
    if (lane == 0) { ps[m >> 5] = fs; ps2[m >> 5] = f2s; }
    __syncthreads();
    if (m == 0) {
        float s = 0.0f, s2 = 0.0f;
#pragma unroll
        for (int w = 0; w < 8; w++) { s += ps[w]; s2 += ps2[w]; }
        atomicAdd(&g_sum[ti],  (double)s);
        atomicAdd(&g_sumsq[ti], (double)s2);
    }
}

// ---------------- kernel 3: finalize stats -------------------------------
__global__ void stats_kernel(const int* __restrict__ tmap) {
    __shared__ float wcnt[8];
    int tid = threadIdx.x;
    float c0 = 0.0f;
    for (int i = tid; i < Nc; i += 256) c0 += (tmap[i] == 0) ? 1.0f : 0.0f;
    c0 = wsum(c0);
    if ((tid & 31) == 0) wcnt[tid >> 5] = c0;
    __syncthreads();
    if (tid == 0) {
        float n0 = 0.0f;
#pragma unroll
        for (int w = 0; w < 8; w++) n0 += wcnt[w];
        int cnt[NTYPESc];
        cnt[0] = (int)(n0 + 0.5f);
        cnt[1] = Nc - cnt[0];
        for (int t = 0; t < NTYPESc; t++) {
            double c   = (double)cnt[t] * Bc * NFEATc;
            double mu  = g_sum[t] / c;
            double var = (g_sumsq[t] - g_sum[t]*g_sum[t]/c) / (c - 1.0);
            g_mu[t]   = (float)mu;
            g_istd[t] = (float)(1.0 / sqrt(var));
        }
    }
}

// ---------------- kernel 4: MLP fwd+bwd, warp-per-2-atoms, fast tanh ------
__device__ __forceinline__ void fma4x2(u64 (&z)[4], float4 wv, float2 xv) {
    u64 x01 = pk2(xv.x, xv.y);
    z[0] = ffma2(pk2(wv.x, wv.x), x01, z[0]);
    z[1] = ffma2(pk2(wv.y, wv.y), x01, z[1]);
    z[2] = ffma2(pk2(wv.z, wv.z), x01, z[2]);
    z[3] = ffma2(pk2(wv.w, wv.w), x01, z[3]);
}

#define MLP_WARPS 4
#define APW 2
__global__ void __launch_bounds__(128) mlp_kernel(
        const int* __restrict__ tmap,
        const float* __restrict__ W0, const float* __restrict__ b0,
        const float* __restrict__ W1, const float* __restrict__ b1,
        const float* __restrict__ W2, const float* __restrict__ b2,
        const float* __restrict__ Wout, const float* __restrict__ bout,
        float* __restrict__ outEi, float* __restrict__ outEtot) {
    __shared__ float2 bufA[MLP_WARPS][Hc];
    __shared__ float2 bufB[MLP_WARPS][Hc];

    const int w   = threadIdx.x >> 5;
    const int ln  = threadIdx.x & 31;
    const int bn0 = (blockIdx.x * MLP_WARPS + w) * APW;
    const int n0  = bn0 & (Nc - 1);
    const int b   = bn0 >> 10;
    const int t   = tmap[n0];
    const float mu = g_mu[t], istd = g_istd[t];

    float*        Af = (float*)bufA[w];
    const float2* A2 = bufA[w];
    const float2* B2 = bufB[w];

#pragma unroll
    for (int k = 0; k < 4; k++) {
        int idx = k * 32 + ln;
        int p = idx >> 1, a = idx & 1;
        Af[idx] = (g_feat[(size_t)(bn0 + a) * NFEATc + p] - mu) * istd;
    }
    __syncwarp();

    const float4* W0f  = (const float4*)(W0    + (size_t)t * NFEATc * Hc);
    const float4* W1f  = (const float4*)(W1    + (size_t)t * Hc * Hc);
    const float4* W2f  = (const float4*)(W2    + (size_t)t * Hc * Hc);
    const float4* W1Tf = (const float4*)(g_W1T + (size_t)t * Hc * Hc);
    const float4* W2Tf = (const float4*)(g_W2T + (size_t)t * Hc * Hc);
    const float2* W0T2 = (const float2*)(g_W0T + (size_t)t * Hc * NFEATc);

    u64 acc2[4];
    float a0r[8], a1r[8], a2r[8], h1r[8];

    // ---- layer 0 ----
    {
        float4 bb = ((const float4*)(b0 + t * Hc))[ln];
        acc2[0] = pk2(bb.x, bb.x);
        acc2[1] = pk2(bb.y, bb.y);
        acc2[2] = pk2(bb.z, bb.z);
        acc2[3] = pk2(bb.w, bb.w);
    }
#pragma unroll 8
    for (int p = 0; p < NFEATc; p++) fma4x2(acc2, W0f[p*32 + ln], A2[p]);
#pragma unroll
    for (int o = 0; o < 4; o++) {
        float u0_, u1_;
        upk2(acc2[o], u0_, u1_);
        a0r[o*2+0] = ftanh(u0_); a0r[o*2+1] = ftanh(u1_);
    }
#pragma unroll
    for (int o = 0; o < 4; o++)
        bufB[w][4*ln + o] = make_float2(a0r[o*2+0], a0r[o*2+1]);
    __syncwarp();

    // ---- layer 1 ----
    {
        float4 bb = ((const float4*)(b1 + t * Hc))[ln];
        acc2[0] = pk2(bb.x, bb.x);
        acc2[1] = pk2(bb.y, bb.y);
        acc2[2] = pk2(bb.z, bb.z);
        acc2[3] = pk2(bb.w, bb.w);
    }
#pragma unroll 8
    for (int p = 0; p < Hc; p++) fma4x2(acc2, W1f[p*32 + ln], B2[p]);
#pragma unroll
    for (int o = 0; o < 4; o++) {
        float u0_, u1_;
        upk2(acc2[o], u0_, u1_);
        a1r[o*2+0] = ftanh(u0_); a1r[o*2+1] = ftanh(u1_);
    }
#pragma unroll
    for (int i = 0; i < 8; i++) h1r[i] = a1r[i] + a0r[i];
#pragma unroll
    for (int o = 0; o < 4; o++)
        bufA[w][4*ln + o] = make_float2(h1r[o*2+0], h1r[o*2+1]);
    __syncwarp();

    // ---- layer 2 ----
    {
        float4 bb = ((const float4*)(b2 + t * Hc))[ln];
        acc2[0] = pk2(bb.x, bb.x);
        acc2[1] = pk2(bb.y, bb.y);
        acc2[2] = pk2(bb.z, bb.z);
        acc2[3] = pk2(bb.w, bb.w);
    }
#pragma unroll 8
    for (int p = 0; p < Hc; p++) fma4x2(acc2, W2f[p*32 + ln], A2[p]);
#pragma unroll
    for (int o = 0; o < 4; o++) {
        float u0_, u1_;
        upk2(acc2[o], u0_, u1_);
        a2r[o*2+0] = ftanh(u0_); a2r[o*2+1] = ftanh(u1_);
    }

    // ---- energy ----
    float4 wo = ((const float4*)(Wout + t * Hc))[ln];
    float e0, e1;
    {
        float h2[8];
#pragma unroll
        for (int i = 0; i < 8; i++) h2[i] = a2r[i] + h1r[i];
        e0 = wo.x*h2[0] + wo.y*h2[2] + wo.z*h2[4] + wo.w*h2[6];
        e1 = wo.x*h2[1] + wo.y*h2[3] + wo.z*h2[5] + wo.w*h2[7];
    }
    e0 = wsum(e0); e1 = wsum(e1);
    float bo = bout[t];
    if (ln < 2) outEi[bn0 + ln] = ((ln == 0) ? e0 : e1) + bo;
    if (ln == 0) atomicAdd(&outEtot[b], e0 + e1 + 2.0f * bo);

    // ---- backward ----
#pragma unroll
    for (int o = 0; o < 4; o++) {
        float wc = (o == 0) ? wo.x : (o == 1) ? wo.y : (o == 2) ? wo.z : wo.w;
        bufB[w][4*ln + o] = make_float2(wc * (1.0f - a2r[o*2+0]*a2r[o*2+0]),
                                        wc * (1.0f - a2r[o*2+1]*a2r[o*2+1]));
    }
    __syncwarp();

    u64 dh2[4];
    dh2[0] = pk2(wo.x, wo.x);
    dh2[1] = pk2(wo.y, wo.y);
    dh2[2] = pk2(wo.z, wo.z);
    dh2[3] = pk2(wo.w, wo.w);
#pragma unroll 8
    for (int j = 0; j < Hc; j++) fma4x2(dh2, W2Tf[j*32 + ln], B2[j]);

#pragma unroll
    for (int o = 0; o < 4; o++) {
        float d0, d1;
        upk2(dh2[o], d0, d1);
        bufA[w][4*ln + o] = make_float2(d0 * (1.0f - a1r[o*2+0]*a1r[o*2+0]),
                                        d1 * (1.0f - a1r[o*2+1]*a1r[o*2+1]));
    }
    __syncwarp();

#pragma unroll 8
    for (int j = 0; j < Hc; j++) fma4x2(dh2, W1Tf[j*32 + ln], A2[j]);

#pragma unroll
    for (int o = 0; o < 4; o++) {
        float d0, d1;
        upk2(dh2[o], d0, d1);
        bufB[w][4*ln + o] = make_float2(d0 * (1.0f - a0r[o*2+0]*a0r[o*2+0]),
                                        d1 * (1.0f - a0r[o*2+1]*a0r[o*2+1]));
    }
    __syncwarp();

    u64 dx0p = 0ULL, dx1p = 0ULL;
#pragma unroll 8
    for (int j = 0; j < Hc; j++) {
        float2 w2 = W0T2[j*32 + ln];
        float2 vv = B2[j];
        u64 v01 = pk2(vv.x, vv.y);
        dx0p = ffma2(pk2(w2.x, w2.x), v01, dx0p);
        dx1p = ffma2(pk2(w2.y, w2.y), v01, dx1p);
    }
    float dx0a, dx0b, dx1a, dx1b;
    upk2(dx0p, dx0a, dx0b);
    upk2(dx1p, dx1a, dx1b);
    ((float2*)g_dfeat)[(size_t)(bn0 + 0) * (NFEATc/2) + ln] =
        make_float2(dx0a * istd, dx1a * istd);
    ((float2*)g_dfeat)[(size_t)(bn0 + 1) * (NFEATc/2) + ln] =
        make_float2(dx0b * istd, dx1b * istd);
}

// ---------------- kernel 5: gradient (factored dsP contraction) ----------
__global__ void grad_kernel(const float* __restrict__ rvec,
                            const int*   __restrict__ tmap,
                            const float* __restrict__ cparam,
                            const int*   __restrict__ list_neigh,
                            float* __restrict__ Force,
                            float* __restrict__ Virial) {
    int bn = blockIdx.x;
    int n  = bn & (Nc - 1);
    int b  = bn >> 10;
    int m  = threadIdx.x;
    int ti = tmap[n];

    __shared__ __align__(16) float ct[NTYPESc*BETAc*M1c];  // [tj][k][p]
    __shared__ float dfs[NFEATc], Ss[NFEATc];
    __shared__ __align__(16) float dsT[4*M1c];             // [a][p]
    __shared__ float acc[12];

    {
        int tjl = m >> 7, rem = m & 127, p = rem >> 3, k = rem & 7;
        ct[tjl*128 + k*16 + p] = cparam[ti * (NTYPESc*M1c*BETAc) + m];
    }
    if (m < NFEATc) {
        dfs[m] = g_dfeat[(long)bn*NFEATc + m];
        Ss[m]  = g_S[(long)bn*NFEATc + m];
    }
    if (m < 12) acc[m] = 0.0f;
    __syncthreads();

    if (m < NFEATc) {
        int r = m >> 2, a = m & 3;
        float v = 0.0f;
#pragma unroll
        for (int q = 0; q < 4; q++) v += dfs[r*4 + q] * Ss[q*4 + a];
        if (r < 4) {
#pragma unroll
            for (int p = 0; p < M1c; p++) v += dfs[p*4 + r] * Ss[p*4 + a];
        }
        dsT[a*M1c + r] = v;
    }
    __syncthreads();

    const float* rv = rvec + ((long)bn * Mc + m) * 3;
    float x = rv[0], y = rv[1], z = rv[2];
    float r2 = x*x + y*y + z*z;
    bool  valid = r2 > 1e-12f;
    float rinv0 = rsqrtf(fmaxf(r2, 1e-30f));
    float rs  = valid ? r2 * rinv0 : 1.0f;
    float inv = valid ? rinv0 : 1.0f;
    float ux = x*inv, uy = y*inv, uz = z*inv;

    float u0 = 2.0f*(rs - RMINc)/SPANc - 1.0f;
    bool  uin = (u0 > -1.0f) && (u0 < 1.0f);
    float u = fminf(fmaxf(u0, -1.0f), 1.0f);
    float rc = fminf(fmaxf(rs, RMINc), RMAXc);
    float arg = PI_F*(rc - RMINc)/SPANc;
    float fc = (valid && rs < RMAXc) ? 0.5f*(__cosf(arg) + 1.0f) : 0.0f;
    float dfc_dr = (valid && rs < RMAXc && rs > RMINc)
                 ? -0.5f*PI_F/SPANc*__sinf(arg) : 0.0f;
    float du_dr  = uin ? 2.0f/SPANc : 0.0f;

    float T[BETAc], D[BETAc];
    T[0] = 1.0f; T[1] = u; D[0] = 0.0f; D[1] = 1.0f;
#pragma unroll
    for (int k = 2; k < BETAc; k++) {
        T[k] = 2.0f*u*T[k-1] - T[k-2];
        D[k] = 2.0f*T[k-1] + 2.0f*u*D[k-1] - D[k-2];
    }

    int tj = m >> 7;
    const u64* cp  = (const u64*)(ct + tj * 128);
    const u64* ds0 = (const u64*)dsT;
    float q0 = valid ? 1.0f : 0.0f;
    float qv[4]; qv[0] = q0; qv[1] = ux*q0; qv[2] = uy*q0; qv[3] = uz*q0;

    // P, Pd (packed over p-pairs); pack T/D on the fly
    u64 P2[8], Pd2[8];
#pragma unroll
    for (int pp = 0; pp < 8; pp++) { P2[pp] = 0ULL; Pd2[pp] = 0ULL; }
#pragma unroll
    for (int k = 0; k < BETAc; k++) {
        u64 tk = pk2(T[k], T[k]);
        u64 dk = pk2(D[k], D[k]);
#pragma unroll
        for (int pp = 0; pp < 8; pp++) {
            u64 c2 = cp[k*8 + pp];
            P2[pp]  = ffma2(c2, tk, P2[pp]);
            Pd2[pp] = ffma2(c2, dk, Pd2[pp]);
        }
    }

    // 8 contractions: dsP[a] = sum_p dS[a][p] P_p, dsPd[a] likewise
    u64 sp2[4], spd2[4];
#pragma unroll
    for (int a = 0; a < 4; a++) { sp2[a] = 0ULL; spd2[a] = 0ULL; }
#pragma unroll
    for (int pp = 0; pp < 8; pp++) {
#pragma unroll
        for (int a = 0; a < 4; a++) {
            u64 d2 = ds0[a*8 + pp];
            sp2[a]  = ffma2(d2, P2[pp],  sp2[a]);
            spd2[a] = ffma2(d2, Pd2[pp], spd2[a]);
        }
    }
    float dsP[4], dsPd[4];
#pragma unroll
    for (int a = 0; a < 4; a++) {
        float lo_, hi_;
        upk2(sp2[a],  lo_, hi_); dsP[a]  = lo_ + hi_;
        upk2(spd2[a], lo_, hi_); dsPd[a] = lo_ + hi_;
    }

    const float invM = 1.0f / Mc;
    float dfc = (qv[0]*dsP[0] + qv[1]*dsP[1] + qv[2]*dsP[2] + qv[3]*dsP[3]) * invM;
    float duP = (qv[0]*dsPd[0] + qv[1]*dsPd[1] + qv[2]*dsPd[2] + qv[3]*dsPd[3]) * invM;
    float dux = dsP[1] * invM * fc * q0;
    float duy = dsP[2] * invM * fc * q0;
    float duz = dsP[3] * invM * fc * q0;

    float du  = fc * duP;
    float drs = dfc * dfc_dr + du * du_dr;
    float dot = dux*ux + duy*uy + duz*uz;

    float fx = 0.0f, fy = 0.0f, fz = 0.0f;
    if (valid) {
        fx = drs*ux + (dux - dot*ux)*inv;
        fy = drs*uy + (duy - dot*uy)*inv;
        fz = drs*uz + (duz - dot*uz)*inv;
    }

    int nb = list_neigh[(long)bn * Mc + m];
    if (nb > 0) {
        long fj = ((long)b * NTOT + (nb - 1)) * 3;
        atomicAdd(&Force[fj + 0], -fx);
        atomicAdd(&Force[fj + 1], -fy);
        atomicAdd(&Force[fj + 2], -fz);
    }

    // center force + virial: 16-component packed butterfly + parity add
    int lane = m & 31;
    float vals[16];
    vals[0] = fx;   vals[1] = fy;   vals[2] = fz;
    vals[3]  = x*fx; vals[4]  = x*fy; vals[5]  = x*fz;
    vals[6]  = y*fx; vals[7]  = y*fy; vals[8]  = y*fz;
    vals[9]  = z*fx; vals[10] = z*fy; vals[11] = z*fz;
    vals[12] = vals[13] = vals[14] = vals[15] = 0.0f;
    bstep<8, 16>(vals, lane);
    bstep<4,  8>(vals, lane);
    bstep<2,  4>(vals, lane);
    bstep<1,  2>(vals, lane);
    vals[0] += __shfl_xor_sync(0xffffffffu, vals[0], 1);
    if ((lane & 1) == 0) {
        int c = (lane >> 1) & 15;
        if (c < 12) atomicAdd(&acc[c], vals[0]);
    }
    __syncthreads();
    if (m < 3)  atomicAdd(&Force[((long)b*NTOT + n)*3 + m], acc[m]);
    if (m >= 3 && m < 12) atomicAdd(&Virial[b*9 + (m - 3)], -acc[m]);
}

// ---------------- launch ---------------------------------------------------
extern "C" void kernel_launch(void* const* d_in, const int* in_sizes, int n_in,
                              void* d_out, int out_size) {
    const int*   list_neigh = (const int*)  d_in[0];
    const int*   tmap       = (const int*)  d_in[1];
    const float* rvec       = (const float*)d_in[2];
    const float* cparam     = (const float*)d_in[3];
    const float* W0         = (const float*)d_in[4];
    const float* b0         = (const float*)d_in[5];
    const float* W1         = (const float*)d_in[6];
    const float* b1         = (const float*)d_in[7];
    const float* W2         = (const float*)d_in[8];
    const float* b2         = (const float*)d_in[9];
    const float* Wout       = (const float*)d_in[10];
    const float* bout       = (const float*)d_in[11];

    float* out      = (float*)d_out;
    float* outEtot  = out + O_ETOT;
    float* outEi    = out + O_EI;
    float* outForce = out + O_FORCE;
    float* outVir   = out + O_VIR;

    prep_kernel<<<(OUT_TOTAL + 255) / 256, 256>>>(out, W0, W1, W2);
    feat_kernel<<<Bc*Nc, 256>>>(rvec, tmap, cparam);
    stats_kernel<<<1, 256>>>(tmap);
    mlp_kernel<<<Bc*Nc / (MLP_WARPS*APW), 128>>>(tmap, W0, b0, W1, b1, W2, b2,
                                                 Wout, bout, outEi, outEtot);
    grad_kernel<<<Bc*Nc, 256>>>(rvec, tmap, cparam, list_neigh, outForce, outVir);
}

// round 13
// speedup vs baseline: 1.1363x; 1.1363x over previous
#include <cuda_runtime.h>
#include <math.h>

#define Bc      8
#define Nc      1024
#define NTYPESc 2
#define MNc     128
#define Mc      256          // NTYPES*MN
#define BETAc   8
#define M1c     16
#define M2c     4
#define NFEATc  64           // M1*M2
#define Hc      128
#define NGHOSTc 64
#define NTOT    (Nc + NGHOSTc)   // 1088
#define RMAXc   6.0f
#define RMINc   0.5f
#define SPANc   5.5f
#define PI_F    3.14159265358979323846f

#define O_ETOT  0
#define O_EI    (O_ETOT + Bc)                 // 8
#define O_FORCE (O_EI + Bc*Nc)                // 8200
#define O_VIR   (O_FORCE + Bc*NTOT*3)         // 34312
#define OUT_TOTAL (O_VIR + Bc*9)              // 34384

typedef unsigned long long u64;

// ---------------- packed f32x2 helpers ----------------
__device__ __forceinline__ u64 pk2(float lo, float hi) {
    u64 r; asm("mov.b64 %0, {%1, %2};" : "=l"(r) : "f"(lo), "f"(hi)); return r;
}
__device__ __forceinline__ void upk2(u64 v, float& lo, float& hi) {
    asm("mov.b64 {%0, %1}, %2;" : "=f"(lo), "=f"(hi) : "l"(v));
}
__device__ __forceinline__ u64 ffma2(u64 a, u64 b, u64 c) {
    u64 d; asm("fma.rn.f32x2 %0, %1, %2, %3;" : "=l"(d) : "l"(a), "l"(b), "l"(c)); return d;
}

// fast tanh via MUFU: tanh(x) = 1 - 2/(exp(2x)+1)
__device__ __forceinline__ float ftanh(float x) {
    float t = __expf(2.0f * x);
    return 1.0f - __fdividef(2.0f, t + 1.0f);
}

// ---------------- device scratch (no allocation allowed) ----------------
__device__ float  g_S    [Bc*Nc*NFEATc];   // S (B,N,16,4), already /M
__device__ float  g_feat [Bc*Nc*NFEATc];   // raw features
__device__ float  g_dfeat[Bc*Nc*NFEATc];   // dE/dfeat_raw (incl. 1/std)
__device__ double g_sum  [NTYPESc];
__device__ double g_sumsq[NTYPESc];
__device__ float  g_mu   [NTYPESc];
__device__ float  g_istd [NTYPESc];        // 1/std
__device__ float  g_W0T  [NTYPESc*Hc*NFEATc];  // [t][j][p]
__device__ float  g_W1T  [NTYPESc*Hc*Hc];      // [t][j][i]
__device__ float  g_W2T  [NTYPESc*Hc*Hc];

__device__ __forceinline__ float wsum(float v) {
    v += __shfl_xor_sync(0xffffffffu, v, 16);
    v += __shfl_xor_sync(0xffffffffu, v, 8);
    v += __shfl_xor_sync(0xffffffffu, v, 4);
    v += __shfl_xor_sync(0xffffffffu, v, 2);
    v += __shfl_xor_sync(0xffffffffu, v, 1);
    return v;
}

// packed butterfly step
template<int HALF, int OFF>
__device__ __forceinline__ void bstep(float* v, int lane) {
    bool hi = (lane & OFF) != 0;
#pragma unroll
    for (int i = 0; i < HALF; i++) {
        float send = hi ? v[i] : v[i + HALF];
        float recv = __shfl_xor_sync(0xffffffffu, send, OFF);
        v[i] = (hi ? v[i + HALF] : v[i]) + recv;
    }
}

// ---------------- kernel 0: zero outputs + transpose weights -------------
__global__ void prep_kernel(float* out,
                            const float* __restrict__ W0,
                            const float* __restrict__ W1,
                            const float* __restrict__ W2) {
    int i = blockIdx.x * blockDim.x + threadIdx.x;
    if (i < OUT_TOTAL) out[i] = 0.0f;
    if (i < NTYPESc) { g_sum[i] = 0.0; g_sumsq[i] = 0.0; }
    if (i < NTYPESc*Hc*NFEATc) {
        int t = i / (Hc*NFEATc); int r = i % (Hc*NFEATc);
        int j = r / NFEATc;      int p = r % NFEATc;
        g_W0T[i] = W0[(t*NFEATc + p)*Hc + j];
    }
    if (i < NTYPESc*Hc*Hc) {
        int t = i / (Hc*Hc); int r = i % (Hc*Hc);
        int j = r / Hc;      int k = r % Hc;
        g_W1T[i] = W1[(t*Hc + k)*Hc + j];
        g_W2T[i] = W2[(t*Hc + k)*Hc + j];
    }
}

// ---------------- kernel 2: features via G-matrix accumulation -----------
// S[p][a] = sum_tj sum_k c[tj][p][k] * G[tj][k][a],
// G[tj][k][a] = sum_{m in tj-half} fc_m * T_mk * q_m[a]
__global__ void feat_kernel(const float* __restrict__ rvec,
                            const int*   __restrict__ tmap,
                            const float* __restrict__ cparam) {
    int bn = blockIdx.x;
    int n  = bn & (Nc - 1);
    int m  = threadIdx.x;
    int ti = tmap[n];

    __shared__ __align__(16) float ct[NTYPESc*BETAc*M1c];  // [tj][k*16+p]
    __shared__ float G_sh[2*32];     // [tj][k*4+a]
    __shared__ float Sn[NFEATc];
    __shared__ float ps[8], ps2[8];

    {   // load c transposed: source index m = tj*128 + p*8 + k
        int tjl = m >> 7, rem = m & 127, p = rem >> 3, k = rem & 7;
        ct[tjl*128 + k*16 + p] = cparam[ti * (NTYPESc*M1c*BETAc) + m];
    }
    if (m < 64) G_sh[m] = 0.0f;
    __syncthreads();

    const float* rv = rvec + ((long)bn * Mc + m) * 3;
    float x = rv[0], y = rv[1], z = rv[2];
    float r2 = x*x + y*y + z*z;
    bool  valid = r2 > 1e-12f;
    float rinv0 = rsqrtf(fmaxf(r2, 1e-30f));
    float rs  = valid ? r2 * rinv0 : 1.0f;
    float inv = valid ? rinv0 : 1.0f;
    float u = 2.0f*(rs - RMINc)/SPANc - 1.0f;
    u = fminf(fmaxf(u, -1.0f), 1.0f);
    float rc = fminf(fmaxf(rs, RMINc), RMAXc);
    float fc = (valid && rs < RMAXc)
             ? 0.5f*(__cosf(PI_F*(rc - RMINc)/SPANc) + 1.0f) : 0.0f;

    float T[BETAc];
    T[0] = 1.0f; T[1] = u;
#pragma unroll
    for (int k = 2; k < BETAc; k++) T[k] = 2.0f*u*T[k-1] - T[k-2];

    float q0 = valid ? 1.0f : 0.0f;
    float qv[4]; qv[0] = q0; qv[1] = x*inv*q0; qv[2] = y*inv*q0; qv[3] = z*inv*q0;

    // outer product fc*T_k*q_a (32 comps), butterfly-reduce, add to G[tj]
    int tj   = m >> 7;        // uniform within a warp
    int lane = m & 31;
    {
        float Tf[BETAc];
#pragma unroll
        for (int k = 0; k < BETAc; k++) Tf[k] = T[k] * fc;
        float v32[32];
#pragma unroll
        for (int k = 0; k < BETAc; k++) {
            v32[k*4 + 0] = Tf[k] * qv[0];
            v32[k*4 + 1] = Tf[k] * qv[1];
            v32[k*4 + 2] = Tf[k] * qv[2];
            v32[k*4 + 3] = Tf[k] * qv[3];
        }
        bstep<16, 16>(v32, lane);
        bstep< 8,  8>(v32, lane);
        bstep< 4,  4>(v32, lane);
        bstep< 2,  2>(v32, lane);
        bstep< 1,  1>(v32, lane);
        // lane holds full warp sum of component lane (k = lane>>2, a = lane&3)
        atomicAdd(&G_sh[tj*32 + lane], v32[0]);
    }
    __syncthreads();

    // S[p][a] = sum_tj sum_k ct[tj][k][p] * G[tj][k][a]
    if (m < NFEATc) {
        int p = m >> 2, a = m & 3;
        float s = 0.0f;
#pragma unroll
        for (int k = 0; k < BETAc; k++) {
            s += ct[      k*16 + p] * G_sh[     k*4 + a];
            s += ct[128 + k*16 + p] * G_sh[32 + k*4 + a];
        }
        s *= (1.0f / Mc);
        Sn[m] = s;
        g_S[(long)bn * NFEATc + m] = s;
    }
    __syncthreads();

    float f = 0.0f;
    if (m < NFEATc) {
        int p = m >> 2, qi = m & 3;
#pragma unroll
        for (int a = 0; a < 4; a++) f += Sn[p*4 + a] * Sn[qi*4 + a];
        g_feat[(long)bn * NFEATc + m] = f;
    }
    float fs  = wsum(f);
    float f2s = wsum(f * f);
    if (lane == 0) { ps[m >> 5] = fs; ps2[m >> 5] = f2s; }
    __syncthreads();
    if (m == 0) {
        float s = 0.0f, s2 = 0.0f;
#pragma unroll
        for (int w = 0; w < 8; w++) { s += ps[w]; s2 += ps2[w]; }
        atomicAdd(&g_sum[ti],  (double)s);
        atomicAdd(&g_sumsq[ti], (double)s2);
    }
}

// ---------------- kernel 3: finalize stats -------------------------------
__global__ void stats_kernel(const int* __restrict__ tmap) {
    __shared__ float wcnt[8];
    int tid = threadIdx.x;
    float c0 = 0.0f;
    for (int i = tid; i < Nc; i += 256) c0 += (tmap[i] == 0) ? 1.0f : 0.0f;
    c0 = wsum(c0);
    if ((tid & 31) == 0) wcnt[tid >> 5] = c0;
    __syncthreads();
    if (tid == 0) {
        float n0 = 0.0f;
#pragma unroll
        for (int w = 0; w < 8; w++) n0 += wcnt[w];
        int cnt[NTYPESc];
        cnt[0] = (int)(n0 + 0.5f);
        cnt[1] = Nc - cnt[0];
        for (int t = 0; t < NTYPESc; t++) {
            double c   = (double)cnt[t] * Bc * NFEATc;
            double mu  = g_sum[t] / c;
            double var = (g_sumsq[t] - g_sum[t]*g_sum[t]/c) / (c - 1.0);
            g_mu[t]   = (float)mu;
            g_istd[t] = (float)(1.0 / sqrt(var));
        }
    }
}

// ---------------- kernel 4: MLP fwd+bwd, warp-per-2-atoms, fast tanh ------
__device__ __forceinline__ void fma4x2(u64 (&z)[4], float4 wv, float2 xv) {
    u64 x01 = pk2(xv.x, xv.y);
    z[0] = ffma2(pk2(wv.x, wv.x), x01, z[0]);
    z[1] = ffma2(pk2(wv.y, wv.y), x01, z[1]);
    z[2] = ffma2(pk2(wv.z, wv.z), x01, z[2]);
    z[3] = ffma2(pk2(wv.w, wv.w), x01, z[3]);
}

#define MLP_WARPS 4
#define APW 2
__global__ void __launch_bounds__(128) mlp_kernel(
        const int* __restrict__ tmap,
        const float* __restrict__ W0, const float* __restrict__ b0,
        const float* __restrict__ W1, const float* __restrict__ b1,
        const float* __restrict__ W2, const float* __restrict__ b2,
        const float* __restrict__ Wout, const float* __restrict__ bout,
        float* __restrict__ outEi, float* __restrict__ outEtot) {
    __shared__ float2 bufA[MLP_WARPS][Hc];
    __shared__ float2 bufB[MLP_WARPS][Hc];

    const int w   = threadIdx.x >> 5;
    const int ln  = threadIdx.x & 31;
    const int bn0 = (blockIdx.x * MLP_WARPS + w) * APW;
    const int n0  = bn0 & (Nc - 1);
    const int b   = bn0 >> 10;
    const int t   = tmap[n0];
    const float mu = g_mu[t], istd = g_istd[t];

    float*        Af = (float*)bufA[w];
    const float2* A2 = bufA[w];
    const float2* B2 = bufB[w];

#pragma unroll
    for (int k = 0; k < 4; k++) {
        int idx = k * 32 + ln;
        int p = idx >> 1, a = idx & 1;
        Af[idx] = (g_feat[(size_t)(bn0 + a) * NFEATc + p] - mu) * istd;
    }
    __syncwarp();

    const float4* W0f  = (const float4*)(W0    + (size_t)t * NFEATc * Hc);
    const float4* W1f  = (const float4*)(W1    + (size_t)t * Hc * Hc);
    const float4* W2f  = (const float4*)(W2    + (size_t)t * Hc * Hc);
    const float4* W1Tf = (const float4*)(g_W1T + (size_t)t * Hc * Hc);
    const float4* W2Tf = (const float4*)(g_W2T + (size_t)t * Hc * Hc);
    const float2* W0T2 = (const float2*)(g_W0T + (size_t)t * Hc * NFEATc);

    u64 acc2[4];
    float a0r[8], a1r[8], a2r[8], h1r[8];

    // ---- layer 0 ----
    {
        float4 bb = ((const float4*)(b0 + t * Hc))[ln];
        acc2[0] = pk2(bb.x, bb.x);
        acc2[1] = pk2(bb.y, bb.y);
        acc2[2] = pk2(bb.z, bb.z);
        acc2[3] = pk2(bb.w, bb.w);
    }
#pragma unroll 8
    for (int p = 0; p < NFEATc; p++) fma4x2(acc2, W0f[p*32 + ln], A2[p]);
#pragma unroll
    for (int o = 0; o < 4; o++) {
        float u0_, u1_;
        upk2(acc2[o], u0_, u1_);
        a0r[o*2+0] = ftanh(u0_); a0r[o*2+1] = ftanh(u1_);
    }
#pragma unroll
    for (int o = 0; o < 4; o++)
        bufB[w][4*ln + o] = make_float2(a0r[o*2+0], a0r[o*2+1]);
    __syncwarp();

    // ---- layer 1 ----
    {
        float4 bb = ((const float4*)(b1 + t * Hc))[ln];
        acc2[0] = pk2(bb.x, bb.x);
        acc2[1] = pk2(bb.y, bb.y);
        acc2[2] = pk2(bb.z, bb.z);
        acc2[3] = pk2(bb.w, bb.w);
    }
#pragma unroll 8
    for (int p = 0; p < Hc; p++) fma4x2(acc2, W1f[p*32 + ln], B2[p]);
#pragma unroll
    for (int o = 0; o < 4; o++) {
        float u0_, u1_;
        upk2(acc2[o], u0_, u1_);
        a1r[o*2+0] = ftanh(u0_); a1r[o*2+1] = ftanh(u1_);
    }
#pragma unroll
    for (int i = 0; i < 8; i++) h1r[i] = a1r[i] + a0r[i];
#pragma unroll
    for (int o = 0; o < 4; o++)
        bufA[w][4*ln + o] = make_float2(h1r[o*2+0], h1r[o*2+1]);
    __syncwarp();

    // ---- layer 2 ----
    {
        float4 bb = ((const float4*)(b2 + t * Hc))[ln];
        acc2[0] = pk2(bb.x, bb.x);
        acc2[1] = pk2(bb.y, bb.y);
        acc2[2] = pk2(bb.z, bb.z);
        acc2[3] = pk2(bb.w, bb.w);
    }
#pragma unroll 8
    for (int p = 0; p < Hc; p++) fma4x2(acc2, W2f[p*32 + ln], A2[p]);
#pragma unroll
    for (int o = 0; o < 4; o++) {
        float u0_, u1_;
        upk2(acc2[o], u0_, u1_);
        a2r[o*2+0] = ftanh(u0_); a2r[o*2+1] = ftanh(u1_);
    }

    // ---- energy ----
    float4 wo = ((const float4*)(Wout + t * Hc))[ln];
    float e0, e1;
    {
        float h2[8];
#pragma unroll
        for (int i = 0; i < 8; i++) h2[i] = a2r[i] + h1r[i];
        e0 = wo.x*h2[0] + wo.y*h2[2] + wo.z*h2[4] + wo.w*h2[6];
        e1 = wo.x*h2[1] + wo.y*h2[3] + wo.z*h2[5] + wo.w*h2[7];
    }
    e0 = wsum(e0); e1 = wsum(e1);
    float bo = bout[t];
    if (ln < 2) outEi[bn0 + ln] = ((ln == 0) ? e0 : e1) + bo;
    if (ln == 0) atomicAdd(&outEtot[b], e0 + e1 + 2.0f * bo);

    // ---- backward ----
#pragma unroll
    for (int o = 0; o < 4; o++) {
        float wc = (o == 0) ? wo.x : (o == 1) ? wo.y : (o == 2) ? wo.z : wo.w;
        bufB[w][4*ln + o] = make_float2(wc * (1.0f - a2r[o*2+0]*a2r[o*2+0]),
                                        wc * (1.0f - a2r[o*2+1]*a2r[o*2+1]));
    }
    __syncwarp();

    u64 dh2[4];
    dh2[0] = pk2(wo.x, wo.x);
    dh2[1] = pk2(wo.y, wo.y);
    dh2[2] = pk2(wo.z, wo.z);
    dh2[3] = pk2(wo.w, wo.w);
#pragma unroll 8
    for (int j = 0; j < Hc; j++) fma4x2(dh2, W2Tf[j*32 + ln], B2[j]);

#pragma unroll
    for (int o = 0; o < 4; o++) {
        float d0, d1;
        upk2(dh2[o], d0, d1);
        bufA[w][4*ln + o] = make_float2(d0 * (1.0f - a1r[o*2+0]*a1r[o*2+0]),
                                        d1 * (1.0f - a1r[o*2+1]*a1r[o*2+1]));
    }
    __syncwarp();

#pragma unroll 8
    for (int j = 0; j < Hc; j++) fma4x2(dh2, W1Tf[j*32 + ln], A2[j]);

#pragma unroll
    for (int o = 0; o < 4; o++) {
        float d0, d1;
        upk2(dh2[o], d0, d1);
        bufB[w][4*ln + o] = make_float2(d0 * (1.0f - a0r[o*2+0]*a0r[o*2+0]),
                                        d1 * (1.0f - a0r[o*2+1]*a0r[o*2+1]));
    }
    __syncwarp();

    u64 dx0p = 0ULL, dx1p = 0ULL;
#pragma unroll 8
    for (int j = 0; j < Hc; j++) {
        float2 w2 = W0T2[j*32 + ln];
        float2 vv = B2[j];
        u64 v01 = pk2(vv.x, vv.y);
        dx0p = ffma2(pk2(w2.x, w2.x), v01, dx0p);
        dx1p = ffma2(pk2(w2.y, w2.y), v01, dx1p);
    }
    float dx0a, dx0b, dx1a, dx1b;
    upk2(dx0p, dx0a, dx0b);
    upk2(dx1p, dx1a, dx1b);
    ((float2*)g_dfeat)[(size_t)(bn0 + 0) * (NFEATc/2) + ln] =
        make_float2(dx0a * istd, dx1a * istd);
    ((float2*)g_dfeat)[(size_t)(bn0 + 1) * (NFEATc/2) + ln] =
        make_float2(dx0b * istd, dx1b * istd);
}

// ---------------- kernel 5: gradient via hoisted e-matrix -----------------
// e[tj][a][k] = sum_p dS[a][p] * c[tj][p][k]  (per atom, computed once);
// per neighbor: dsP[a] = sum_k T_k e, dsPd[a] = sum_k D_k e (packed).
__global__ void grad_kernel(const float* __restrict__ rvec,
                            const int*   __restrict__ tmap,
                            const float* __restrict__ cparam,
                            const int*   __restrict__ list_neigh,
                            float* __restrict__ Force,
                            float* __restrict__ Virial) {
    int bn = blockIdx.x;
    int n  = bn & (Nc - 1);
    int b  = bn >> 10;
    int m  = threadIdx.x;
    int ti = tmap[n];

    __shared__ __align__(16) float ct[NTYPESc*BETAc*M1c];  // [tj][k*16+p]
    __shared__ float dfs[NFEATc], Ss[NFEATc];
    __shared__ __align__(16) float dsT[4*M1c];             // [a][p]
    __shared__ u64   e2_sh[2*32];                          // [tj][a*8+k], (e,e)
    __shared__ float acc[12];

    {
        int tjl = m >> 7, rem = m & 127, p = rem >> 3, k = rem & 7;
        ct[tjl*128 + k*16 + p] = cparam[ti * (NTYPESc*M1c*BETAc) + m];
    }
    if (m < NFEATc) {
        dfs[m] = g_dfeat[(long)bn*NFEATc + m];
        Ss[m]  = g_S[(long)bn*NFEATc + m];
    }
    if (m < 12) acc[m] = 0.0f;
    __syncthreads();

    if (m < NFEATc) {
        int r = m >> 2, a = m & 3;
        float v = 0.0f;
#pragma unroll
        for (int q = 0; q < 4; q++) v += dfs[r*4 + q] * Ss[q*4 + a];
        if (r < 4) {
#pragma unroll
            for (int p = 0; p < M1c; p++) v += dfs[p*4 + r] * Ss[p*4 + a];
        }
        dsT[a*M1c + r] = v;
    }
    __syncthreads();

    // e[tj][a][k] = sum_p dsT[a][p] * ct[tj][k][p]
    if (m < 64) {
        int tjl = m >> 5, r = m & 31, a = r >> 3, k = r & 7;
        float e = 0.0f;
        const float* cr = ct + tjl*128 + k*16;
        const float* dr = dsT + a*M1c;
#pragma unroll
        for (int p = 0; p < M1c; p++) e += dr[p] * cr[p];
        e2_sh[m] = pk2(e, e);
    }
    __syncthreads();

    const float* rv = rvec + ((long)bn * Mc + m) * 3;
    float x = rv[0], y = rv[1], z = rv[2];
    float r2 = x*x + y*y + z*z;
    bool  valid = r2 > 1e-12f;
    float rinv0 = rsqrtf(fmaxf(r2, 1e-30f));
    float rs  = valid ? r2 * rinv0 : 1.0f;
    float inv = valid ? rinv0 : 1.0f;
    float ux = x*inv, uy = y*inv, uz = z*inv;

    float u0 = 2.0f*(rs - RMINc)/SPANc - 1.0f;
    bool  uin = (u0 > -1.0f) && (u0 < 1.0f);
    float u = fminf(fmaxf(u0, -1.0f), 1.0f);
    float rc = fminf(fmaxf(rs, RMINc), RMAXc);
    float arg = PI_F*(rc - RMINc)/SPANc;
    float fc = (valid && rs < RMAXc) ? 0.5f*(__cosf(arg) + 1.0f) : 0.0f;
    float dfc_dr = (valid && rs < RMAXc && rs > RMINc)
                 ? -0.5f*PI_F/SPANc*__sinf(arg) : 0.0f;
    float du_dr  = uin ? 2.0f/SPANc : 0.0f;

    float T[BETAc], D[BETAc];
    T[0] = 1.0f; T[1] = u; D[0] = 0.0f; D[1] = 1.0f;
#pragma unroll
    for (int k = 2; k < BETAc; k++) {
        T[k] = 2.0f*u*T[k-1] - T[k-2];
        D[k] = 2.0f*T[k-1] + 2.0f*u*D[k-1] - D[k-2];
    }

    int tj = m >> 7;
    const u64* ee = e2_sh + tj*32;
    float q0 = valid ? 1.0f : 0.0f;
    float qv[4]; qv[0] = q0; qv[1] = ux*q0; qv[2] = uy*q0; qv[3] = uz*q0;

    // packed (dsP, dsPd) accumulators: 32 FFMA2 total
    u64 accA[4];
#pragma unroll
    for (int a = 0; a < 4; a++) accA[a] = 0ULL;
#pragma unroll
    for (int k = 0; k < BETAc; k++) {
        u64 td = pk2(T[k], D[k]);
#pragma unroll
        for (int a = 0; a < 4; a++) accA[a] = ffma2(ee[a*8 + k], td, accA[a]);
    }
    float dsP[4], dsPd[4];
#pragma unroll
    for (int a = 0; a < 4; a++) upk2(accA[a], dsP[a], dsPd[a]);

    const float invM = 1.0f / Mc;
    float dfc = (qv[0]*dsP[0] + qv[1]*dsP[1] + qv[2]*dsP[2] + qv[3]*dsP[3]) * invM;
    float duP = (qv[0]*dsPd[0] + qv[1]*dsPd[1] + qv[2]*dsPd[2] + qv[3]*dsPd[3]) * invM;
    float dux = dsP[1] * invM * fc * q0;
    float duy = dsP[2] * invM * fc * q0;
    float duz = dsP[3] * invM * fc * q0;

    float du  = fc * duP;
    float drs = dfc * dfc_dr + du * du_dr;
    float dot = dux*ux + duy*uy + duz*uz;

    float fx = 0.0f, fy = 0.0f, fz = 0.0f;
    if (valid) {
        fx = drs*ux + (dux - dot*ux)*inv;
        fy = drs*uy + (duy - dot*uy)*inv;
        fz = drs*uz + (duz - dot*uz)*inv;
    }

    int nb = list_neigh[(long)bn * Mc + m];
    if (nb > 0) {
        long fj = ((long)b * NTOT + (nb - 1)) * 3;
        atomicAdd(&Force[fj + 0], -fx);
        atomicAdd(&Force[fj + 1], -fy);
        atomicAdd(&Force[fj + 2], -fz);
    }

    // center force + virial: 16-component packed butterfly + parity add
    int lane = m & 31;
    float vals[16];
    vals[0] = fx;   vals[1] = fy;   vals[2] = fz;
    vals[3]  = x*fx; vals[4]  = x*fy; vals[5]  = x*fz;
    vals[6]  = y*fx; vals[7]  = y*fy; vals[8]  = y*fz;
    vals[9]  = z*fx; vals[10] = z*fy; vals[11] = z*fz;
    vals[12] = vals[13] = vals[14] = vals[15] = 0.0f;
    bstep<8, 16>(vals, lane);
    bstep<4,  8>(vals, lane);
    bstep<2,  4>(vals, lane);
    bstep<1,  2>(vals, lane);
    vals[0] += __shfl_xor_sync(0xffffffffu, vals[0], 1);
    if ((lane & 1) == 0) {
        int c = (lane >> 1) & 15;
        if (c < 12) atomicAdd(&acc[c], vals[0]);
    }
    __syncthreads();
    if (m < 3)  atomicAdd(&Force[((long)b*NTOT + n)*3 + m], acc[m]);
    if (m >= 3 && m < 12) atomicAdd(&Virial[b*9 + (m - 3)], -acc[m]);
}

// ---------------- launch ---------------------------------------------------
extern "C" void kernel_launch(void* const* d_in, const int* in_sizes, int n_in,
                              void* d_out, int out_size) {
    const int*   list_neigh = (const int*)  d_in[0];
    const int*   tmap       = (const int*)  d_in[1];
    const float* rvec       = (const float*)d_in[2];
    const float* cparam     = (const float*)d_in[3];
    const float* W0         = (const float*)d_in[4];
    const float* b0         = (const float*)d_in[5];
    const float* W1         = (const float*)d_in[6];
    const float* b1         = (const float*)d_in[7];
    const float* W2         = (const float*)d_in[8];
    const float* b2         = (const float*)d_in[9];
    const float* Wout       = (const float*)d_in[10];
    const float* bout       = (const float*)d_in[11];

    float* out      = (float*)d_out;
    float* outEtot  = out + O_ETOT;
    float* outEi    = out + O_EI;
    float* outForce = out + O_FORCE;
    float* outVir   = out + O_VIR;

    prep_kernel<<<(OUT_TOTAL + 255) / 256, 256>>>(out, W0, W1, W2);
    feat_kernel<<<Bc*Nc, 256>>>(rvec, tmap, cparam);
    stats_kernel<<<1, 256>>>(tmap);
    mlp_kernel<<<Bc*Nc / (MLP_WARPS*APW), 128>>>(tmap, W0, b0, W1, b1, W2, b2,
                                                 Wout, bout, outEi, outEtot);
    grad_kernel<<<Bc*Nc, 256>>>(rvec, tmap, cparam, list_neigh, outForce, outVir);
}

// round 14
// speedup vs baseline: 1.2530x; 1.1027x over previous
#include <cuda_runtime.h>
#include <math.h>

#define Bc      8
#define Nc      1024
#define NTYPESc 2
#define MNc     128
#define Mc      256          // NTYPES*MN
#define BETAc   8
#define M1c     16
#define M2c     4
#define NFEATc  64           // M1*M2
#define Hc      128
#define NGHOSTc 64
#define NTOT    (Nc + NGHOSTc)   // 1088
#define RMAXc   6.0f
#define RMINc   0.5f
#define SPANc   5.5f
#define PI_F    3.14159265358979323846f

#define O_ETOT  0
#define O_EI    (O_ETOT + Bc)                 // 8
#define O_FORCE (O_EI + Bc*Nc)                // 8200
#define O_VIR   (O_FORCE + Bc*NTOT*3)         // 34312
#define OUT_TOTAL (O_VIR + Bc*9)              // 34384

typedef unsigned long long u64;

// ---------------- packed f32x2 helpers ----------------
__device__ __forceinline__ u64 pk2(float lo, float hi) {
    u64 r; asm("mov.b64 %0, {%1, %2};" : "=l"(r) : "f"(lo), "f"(hi)); return r;
}
__device__ __forceinline__ void upk2(u64 v, float& lo, float& hi) {
    asm("mov.b64 {%0, %1}, %2;" : "=f"(lo), "=f"(hi) : "l"(v));
}
__device__ __forceinline__ u64 ffma2(u64 a, u64 b, u64 c) {
    u64 d; asm("fma.rn.f32x2 %0, %1, %2, %3;" : "=l"(d) : "l"(a), "l"(b), "l"(c)); return d;
}

// fast tanh via MUFU: tanh(x) = 1 - 2/(exp(2x)+1)
__device__ __forceinline__ float ftanh(float x) {
    float t = __expf(2.0f * x);
    return 1.0f - __fdividef(2.0f, t + 1.0f);
}

// ---------------- device scratch (no allocation allowed) ----------------
__device__ float  g_S    [Bc*Nc*NFEATc];   // S (B,N,16,4), already /M
__device__ float  g_feat [Bc*Nc*NFEATc];   // raw features
__device__ float  g_dfeat[Bc*Nc*NFEATc];   // dE/dfeat_raw (incl. 1/std)
__device__ double g_sum  [NTYPESc];
__device__ double g_sumsq[NTYPESc];
__device__ float  g_mu   [NTYPESc];
__device__ float  g_istd [NTYPESc];        // 1/std
__device__ float  g_W0T  [NTYPESc*Hc*NFEATc];  // [t][j][p]
__device__ float  g_W1T  [NTYPESc*Hc*Hc];      // [t][j][i]
__device__ float  g_W2T  [NTYPESc*Hc*Hc];

__device__ __forceinline__ float wsum(float v) {
    v += __shfl_xor_sync(0xffffffffu, v, 16);
    v += __shfl_xor_sync(0xffffffffu, v, 8);
    v += __shfl_xor_sync(0xffffffffu, v, 4);
    v += __shfl_xor_sync(0xffffffffu, v, 2);
    v += __shfl_xor_sync(0xffffffffu, v, 1);
    return v;
}

// packed butterfly step
template<int HALF, int OFF>
__device__ __forceinline__ void bstep(float* v, int lane) {
    bool hi = (lane & OFF) != 0;
#pragma unroll
    for (int i = 0; i < HALF; i++) {
        float send = hi ? v[i] : v[i + HALF];
        float recv = __shfl_xor_sync(0xffffffffu, send, OFF);
        v[i] = (hi ? v[i + HALF] : v[i]) + recv;
    }
}

// ---------------- kernel 0: zero outputs + transpose weights -------------
__global__ void prep_kernel(float* out,
                            const float* __restrict__ W0,
                            const float* __restrict__ W1,
                            const float* __restrict__ W2) {
    int i = blockIdx.x * blockDim.x + threadIdx.x;
    if (i < OUT_TOTAL) out[i] = 0.0f;
    if (i < NTYPESc) { g_sum[i] = 0.0; g_sumsq[i] = 0.0; }
    if (i < NTYPESc*Hc*NFEATc) {
        int t = i / (Hc*NFEATc); int r = i % (Hc*NFEATc);
        int j = r / NFEATc;      int p = r % NFEATc;
        g_W0T[i] = W0[(t*NFEATc + p)*Hc + j];
    }
    if (i < NTYPESc*Hc*Hc) {
        int t = i / (Hc*Hc); int r = i % (Hc*Hc);
        int j = r / Hc;      int k = r % Hc;
        g_W1T[i] = W1[(t*Hc + k)*Hc + j];
        g_W2T[i] = W2[(t*Hc + k)*Hc + j];
    }
}

// ---------------- kernel 2: features, 128 thr, 2 neighbors/thread --------
// thread t handles neighbors 2t, 2t+1 (same tj: tj = t>>6)
__global__ void feat_kernel(const float* __restrict__ rvec,
                            const int*   __restrict__ tmap,
                            const float* __restrict__ cparam) {
    int bn  = blockIdx.x;
    int n   = bn & (Nc - 1);
    int t   = threadIdx.x;      // 0..127
    int ti  = tmap[n];

    __shared__ __align__(16) float ct[NTYPESc*BETAc*M1c];  // [tj][k*16+p]
    __shared__ float G_sh[2*32];     // [tj][k*4+a]
    __shared__ float Sn[NFEATc];
    __shared__ float ps[4], ps2[4];

    {   // load c transposed (each thread loads 2): src idx i = tj*128 + p*8 + k
#pragma unroll
        for (int i = t; i < 256; i += 128) {
            int tjl = i >> 7, rem = i & 127, p = rem >> 3, k = rem & 7;
            ct[tjl*128 + k*16 + p] = cparam[ti * (NTYPESc*M1c*BETAc) + i];
        }
    }
    if (t < 64) G_sh[t] = 0.0f;
    __syncthreads();

    int tj   = t >> 6;
    int lane = t & 31;

    float v32[32];
#pragma unroll
    for (int i = 0; i < 32; i++) v32[i] = 0.0f;

#pragma unroll
    for (int s = 0; s < 2; s++) {
        int m = 2*t + s;
        const float* rv = rvec + ((long)bn * Mc + m) * 3;
        float x = rv[0], y = rv[1], z = rv[2];
        float r2 = x*x + y*y + z*z;
        bool  valid = r2 > 1e-12f;
        float rinv0 = rsqrtf(fmaxf(r2, 1e-30f));
        float rs  = valid ? r2 * rinv0 : 1.0f;
        float inv = valid ? rinv0 : 1.0f;
        float u = 2.0f*(rs - RMINc)/SPANc - 1.0f;
        u = fminf(fmaxf(u, -1.0f), 1.0f);
        float rc = fminf(fmaxf(rs, RMINc), RMAXc);
        float fc = (valid && rs < RMAXc)
                 ? 0.5f*(__cosf(PI_F*(rc - RMINc)/SPANc) + 1.0f) : 0.0f;

        float T[BETAc];
        T[0] = 1.0f; T[1] = u;
#pragma unroll
        for (int k = 2; k < BETAc; k++) T[k] = 2.0f*u*T[k-1] - T[k-2];

        float q0 = valid ? 1.0f : 0.0f;
        float qv[4]; qv[0] = q0; qv[1] = x*inv*q0; qv[2] = y*inv*q0; qv[3] = z*inv*q0;

#pragma unroll
        for (int k = 0; k < BETAc; k++) {
            float Tf = T[k] * fc;
            v32[k*4 + 0] = fmaf(Tf, qv[0], v32[k*4 + 0]);
            v32[k*4 + 1] = fmaf(Tf, qv[1], v32[k*4 + 1]);
            v32[k*4 + 2] = fmaf(Tf, qv[2], v32[k*4 + 2]);
            v32[k*4 + 3] = fmaf(Tf, qv[3], v32[k*4 + 3]);
        }
    }

    bstep<16, 16>(v32, lane);
    bstep< 8,  8>(v32, lane);
    bstep< 4,  4>(v32, lane);
    bstep< 2,  2>(v32, lane);
    bstep< 1,  1>(v32, lane);
    atomicAdd(&G_sh[tj*32 + lane], v32[0]);
    __syncthreads();

    // S[p][a] = sum_tj sum_k ct[tj][k][p] * G[tj][k][a]
    if (t < NFEATc) {
        int p = t >> 2, a = t & 3;
        float s = 0.0f;
#pragma unroll
        for (int k = 0; k < BETAc; k++) {
            s += ct[      k*16 + p] * G_sh[     k*4 + a];
            s += ct[128 + k*16 + p] * G_sh[32 + k*4 + a];
        }
        s *= (1.0f / Mc);
        Sn[t] = s;
        g_S[(long)bn * NFEATc + t] = s;
    }
    __syncthreads();

    float f = 0.0f;
    if (t < NFEATc) {
        int p = t >> 2, qi = t & 3;
#pragma unroll
        for (int a = 0; a < 4; a++) f += Sn[p*4 + a] * Sn[qi*4 + a];
        g_feat[(long)bn * NFEATc + t] = f;
    }
    float fs  = wsum(f);
    float f2s = wsum(f * f);
    if (lane == 0) { ps[t >> 5] = fs; ps2[t >> 5] = f2s; }
    __syncthreads();
    if (t == 0) {
        float s = 0.0f, s2 = 0.0f;
#pragma unroll
        for (int w = 0; w < 4; w++) { s += ps[w]; s2 += ps2[w]; }
        atomicAdd(&g_sum[ti],  (double)s);
        atomicAdd(&g_sumsq[ti], (double)s2);
    }
}

// ---------------- kernel 3: finalize stats -------------------------------
__global__ void stats_kernel(const int* __restrict__ tmap) {
    __shared__ float wcnt[8];
    int tid = threadIdx.x;
    float c0 = 0.0f;
    for (int i = tid; i < Nc; i += 256) c0 += (tmap[i] == 0) ? 1.0f : 0.0f;
    c0 = wsum(c0);
    if ((tid & 31) == 0) wcnt[tid >> 5] = c0;
    __syncthreads();
    if (tid == 0) {
        float n0 = 0.0f;
#pragma unroll
        for (int w = 0; w < 8; w++) n0 += wcnt[w];
        int cnt[NTYPESc];
        cnt[0] = (int)(n0 + 0.5f);
        cnt[1] = Nc - cnt[0];
        for (int t = 0; t < NTYPESc; t++) {
            double c   = (double)cnt[t] * Bc * NFEATc;
            double mu  = g_sum[t] / c;
            double var = (g_sumsq[t] - g_sum[t]*g_sum[t]/c) / (c - 1.0);
            g_mu[t]   = (float)mu;
            g_istd[t] = (float)(1.0 / sqrt(var));
        }
    }
}

// ---------------- kernel 4: MLP fwd+bwd, warp-per-2-atoms, fast tanh ------
__device__ __forceinline__ void fma4x2(u64 (&z)[4], float4 wv, float2 xv) {
    u64 x01 = pk2(xv.x, xv.y);
    z[0] = ffma2(pk2(wv.x, wv.x), x01, z[0]);
    z[1] = ffma2(pk2(wv.y, wv.y), x01, z[1]);
    z[2] = ffma2(pk2(wv.z, wv.z), x01, z[2]);
    z[3] = ffma2(pk2(wv.w, wv.w), x01, z[3]);
}

#define MLP_WARPS 4
#define APW 2
__global__ void __launch_bounds__(128) mlp_kernel(
        const int* __restrict__ tmap,
        const float* __restrict__ W0, const float* __restrict__ b0,
        const float* __restrict__ W1, const float* __restrict__ b1,
        const float* __restrict__ W2, const float* __restrict__ b2,
        const float* __restrict__ Wout, const float* __restrict__ bout,
        float* __restrict__ outEi, float* __restrict__ outEtot) {
    __shared__ float2 bufA[MLP_WARPS][Hc];
    __shared__ float2 bufB[MLP_WARPS][Hc];

    const int w   = threadIdx.x >> 5;
    const int ln  = threadIdx.x & 31;
    const int bn0 = (blockIdx.x * MLP_WARPS + w) * APW;
    const int n0  = bn0 & (Nc - 1);
    const int b   = bn0 >> 10;
    const int t   = tmap[n0];
    const float mu = g_mu[t], istd = g_istd[t];

    float*        Af = (float*)bufA[w];
    const float2* A2 = bufA[w];
    const float2* B2 = bufB[w];

#pragma unroll
    for (int k = 0; k < 4; k++) {
        int idx = k * 32 + ln;
        int p = idx >> 1, a = idx & 1;
        Af[idx] = (g_feat[(size_t)(bn0 + a) * NFEATc + p] - mu) * istd;
    }
    __syncwarp();

    const float4* W0f  = (const float4*)(W0    + (size_t)t * NFEATc * Hc);
    const float4* W1f  = (const float4*)(W1    + (size_t)t * Hc * Hc);
    const float4* W2f  = (const float4*)(W2    + (size_t)t * Hc * Hc);
    const float4* W1Tf = (const float4*)(g_W1T + (size_t)t * Hc * Hc);
    const float4* W2Tf = (const float4*)(g_W2T + (size_t)t * Hc * Hc);
    const float2* W0T2 = (const float2*)(g_W0T + (size_t)t * Hc * NFEATc);

    u64 acc2[4];
    float a0r[8], a1r[8], a2r[8], h1r[8];

    // ---- layer 0 ----
    {
        float4 bb = ((const float4*)(b0 + t * Hc))[ln];
        acc2[0] = pk2(bb.x, bb.x);
        acc2[1] = pk2(bb.y, bb.y);
        acc2[2] = pk2(bb.z, bb.z);
        acc2[3] = pk2(bb.w, bb.w);
    }
#pragma unroll 8
    for (int p = 0; p < NFEATc; p++) fma4x2(acc2, W0f[p*32 + ln], A2[p]);
#pragma unroll
    for (int o = 0; o < 4; o++) {
        float u0_, u1_;
        upk2(acc2[o], u0_, u1_);
        a0r[o*2+0] = ftanh(u0_); a0r[o*2+1] = ftanh(u1_);
    }
#pragma unroll
    for (int o = 0; o < 4; o++)
        bufB[w][4*ln + o] = make_float2(a0r[o*2+0], a0r[o*2+1]);
    __syncwarp();

    // ---- layer 1 ----
    {
        float4 bb = ((const float4*)(b1 + t * Hc))[ln];
        acc2[0] = pk2(bb.x, bb.x);
        acc2[1] = pk2(bb.y, bb.y);
        acc2[2] = pk2(bb.z, bb.z);
        acc2[3] = pk2(bb.w, bb.w);
    }
#pragma unroll 8
    for (int p = 0; p < Hc; p++) fma4x2(acc2, W1f[p*32 + ln], B2[p]);
#pragma unroll
    for (int o = 0; o < 4; o++) {
        float u0_, u1_;
        upk2(acc2[o], u0_, u1_);
        a1r[o*2+0] = ftanh(u0_); a1r[o*2+1] = ftanh(u1_);
    }
#pragma unroll
    for (int i = 0; i < 8; i++) h1r[i] = a1r[i] + a0r[i];
#pragma unroll
    for (int o = 0; o < 4; o++)
        bufA[w][4*ln + o] = make_float2(h1r[o*2+0], h1r[o*2+1]);
    __syncwarp();

    // ---- layer 2 ----
    {
        float4 bb = ((const float4*)(b2 + t * Hc))[ln];
        acc2[0] = pk2(bb.x, bb.x);
        acc2[1] = pk2(bb.y, bb.y);
        acc2[2] = pk2(bb.z, bb.z);
        acc2[3] = pk2(bb.w, bb.w);
    }
#pragma unroll 8
    for (int p = 0; p < Hc; p++) fma4x2(acc2, W2f[p*32 + ln], A2[p]);
#pragma unroll
    for (int o = 0; o < 4; o++) {
        float u0_, u1_;
        upk2(acc2[o], u0_, u1_);
        a2r[o*2+0] = ftanh(u0_); a2r[o*2+1] = ftanh(u1_);
    }

    // ---- energy ----
    float4 wo = ((const float4*)(Wout + t * Hc))[ln];
    float e0, e1;
    {
        float h2[8];
#pragma unroll
        for (int i = 0; i < 8; i++) h2[i] = a2r[i] + h1r[i];
        e0 = wo.x*h2[0] + wo.y*h2[2] + wo.z*h2[4] + wo.w*h2[6];
        e1 = wo.x*h2[1] + wo.y*h2[3] + wo.z*h2[5] + wo.w*h2[7];
    }
    e0 = wsum(e0); e1 = wsum(e1);
    float bo = bout[t];
    if (ln < 2) outEi[bn0 + ln] = ((ln == 0) ? e0 : e1) + bo;
    if (ln == 0) atomicAdd(&outEtot[b], e0 + e1 + 2.0f * bo);

    // ---- backward ----
#pragma unroll
    for (int o = 0; o < 4; o++) {
        float wc = (o == 0) ? wo.x : (o == 1) ? wo.y : (o == 2) ? wo.z : wo.w;
        bufB[w][4*ln + o] = make_float2(wc * (1.0f - a2r[o*2+0]*a2r[o*2+0]),
                                        wc * (1.0f - a2r[o*2+1]*a2r[o*2+1]));
    }
    __syncwarp();

    u64 dh2[4];
    dh2[0] = pk2(wo.x, wo.x);
    dh2[1] = pk2(wo.y, wo.y);
    dh2[2] = pk2(wo.z, wo.z);
    dh2[3] = pk2(wo.w, wo.w);
#pragma unroll 8
    for (int j = 0; j < Hc; j++) fma4x2(dh2, W2Tf[j*32 + ln], B2[j]);

#pragma unroll
    for (int o = 0; o < 4; o++) {
        float d0, d1;
        upk2(dh2[o], d0, d1);
        bufA[w][4*ln + o] = make_float2(d0 * (1.0f - a1r[o*2+0]*a1r[o*2+0]),
                                        d1 * (1.0f - a1r[o*2+1]*a1r[o*2+1]));
    }
    __syncwarp();

#pragma unroll 8
    for (int j = 0; j < Hc; j++) fma4x2(dh2, W1Tf[j*32 + ln], A2[j]);

#pragma unroll
    for (int o = 0; o < 4; o++) {
        float d0, d1;
        upk2(dh2[o], d0, d1);
        bufB[w][4*ln + o] = make_float2(d0 * (1.0f - a0r[o*2+0]*a0r[o*2+0]),
                                        d1 * (1.0f - a0r[o*2+1]*a0r[o*2+1]));
    }
    __syncwarp();

    u64 dx0p = 0ULL, dx1p = 0ULL;
#pragma unroll 8
    for (int j = 0; j < Hc; j++) {
        float2 w2 = W0T2[j*32 + ln];
        float2 vv = B2[j];
        u64 v01 = pk2(vv.x, vv.y);
        dx0p = ffma2(pk2(w2.x, w2.x), v01, dx0p);
        dx1p = ffma2(pk2(w2.y, w2.y), v01, dx1p);
    }
    float dx0a, dx0b, dx1a, dx1b;
    upk2(dx0p, dx0a, dx0b);
    upk2(dx1p, dx1a, dx1b);
    ((float2*)g_dfeat)[(size_t)(bn0 + 0) * (NFEATc/2) + ln] =
        make_float2(dx0a * istd, dx1a * istd);
    ((float2*)g_dfeat)[(size_t)(bn0 + 1) * (NFEATc/2) + ln] =
        make_float2(dx0b * istd, dx1b * istd);
}

// ---------------- kernel 5: gradient, 128 thr, 2 neighbors/thread --------
__global__ void grad_kernel(const float* __restrict__ rvec,
                            const int*   __restrict__ tmap,
                            const float* __restrict__ cparam,
                            const int*   __restrict__ list_neigh,
                            float* __restrict__ Force,
                            float* __restrict__ Virial) {
    int bn = blockIdx.x;
    int n  = bn & (Nc - 1);
    int b  = bn >> 10;
    int t  = threadIdx.x;      // 0..127
    int ti = tmap[n];

    __shared__ __align__(16) float ct[NTYPESc*BETAc*M1c];  // [tj][k*16+p]
    __shared__ float dfs[NFEATc], Ss[NFEATc];
    __shared__ __align__(16) float dsT[4*M1c];             // [a][p]
    __shared__ u64   e2_sh[2*32];                          // [tj][a*8+k], (e,e)
    __shared__ float acc[12];

    {
#pragma unroll
        for (int i = t; i < 256; i += 128) {
            int tjl = i >> 7, rem = i & 127, p = rem >> 3, k = rem & 7;
            ct[tjl*128 + k*16 + p] = cparam[ti * (NTYPESc*M1c*BETAc) + i];
        }
    }
    if (t < NFEATc) {
        dfs[t] = g_dfeat[(long)bn*NFEATc + t];
        Ss[t]  = g_S[(long)bn*NFEATc + t];
    }
    if (t < 12) acc[t] = 0.0f;
    __syncthreads();

    if (t < NFEATc) {
        int r = t >> 2, a = t & 3;
        float v = 0.0f;
#pragma unroll
        for (int q = 0; q < 4; q++) v += dfs[r*4 + q] * Ss[q*4 + a];
        if (r < 4) {
#pragma unroll
            for (int p = 0; p < M1c; p++) v += dfs[p*4 + r] * Ss[p*4 + a];
        }
        dsT[a*M1c + r] = v;
    }
    __syncthreads();

    // e[tj][a][k] = sum_p dsT[a][p] * ct[tj][k][p]
    if (t < 64) {
        int tjl = t >> 5, r = t & 31, a = r >> 3, k = r & 7;
        float e = 0.0f;
        const float* cr = ct + tjl*128 + k*16;
        const float* dr = dsT + a*M1c;
#pragma unroll
        for (int p = 0; p < M1c; p++) e += dr[p] * cr[p];
        e2_sh[t] = pk2(e, e);
    }
    __syncthreads();

    int tj = t >> 6;
    const u64* ee = e2_sh + tj*32;
    const float invM = 1.0f / Mc;

    float vals[16];
#pragma unroll
    for (int i = 0; i < 16; i++) vals[i] = 0.0f;

#pragma unroll
    for (int s = 0; s < 2; s++) {
        int m = 2*t + s;
        const float* rv = rvec + ((long)bn * Mc + m) * 3;
        float x = rv[0], y = rv[1], z = rv[2];
        float r2 = x*x + y*y + z*z;
        bool  valid = r2 > 1e-12f;
        float rinv0 = rsqrtf(fmaxf(r2, 1e-30f));
        float rs  = valid ? r2 * rinv0 : 1.0f;
        float inv = valid ? rinv0 : 1.0f;
        float ux = x*inv, uy = y*inv, uz = z*inv;

        float u0 = 2.0f*(rs - RMINc)/SPANc - 1.0f;
        bool  uin = (u0 > -1.0f) && (u0 < 1.0f);
        float u = fminf(fmaxf(u0, -1.0f), 1.0f);
        float rc = fminf(fmaxf(rs, RMINc), RMAXc);
        float arg = PI_F*(rc - RMINc)/SPANc;
        float fc = (valid && rs < RMAXc) ? 0.5f*(__cosf(arg) + 1.0f) : 0.0f;
        float dfc_dr = (valid && rs < RMAXc && rs > RMINc)
                     ? -0.5f*PI_F/SPANc*__sinf(arg) : 0.0f;
        float du_dr  = uin ? 2.0f/SPANc : 0.0f;

        float T[BETAc], D[BETAc];
        T[0] = 1.0f; T[1] = u; D[0] = 0.0f; D[1] = 1.0f;
#pragma unroll
        for (int k = 2; k < BETAc; k++) {
            T[k] = 2.0f*u*T[k-1] - T[k-2];
            D[k] = 2.0f*T[k-1] + 2.0f*u*D[k-1] - D[k-2];
        }

        float q0 = valid ? 1.0f : 0.0f;
        float qv[4]; qv[0] = q0; qv[1] = ux*q0; qv[2] = uy*q0; qv[3] = uz*q0;

        u64 accA[4];
#pragma unroll
        for (int a = 0; a < 4; a++) accA[a] = 0ULL;
#pragma unroll
        for (int k = 0; k < BETAc; k++) {
            u64 td = pk2(T[k], D[k]);
#pragma unroll
            for (int a = 0; a < 4; a++) accA[a] = ffma2(ee[a*8 + k], td, accA[a]);
        }
        float dsP[4], dsPd[4];
#pragma unroll
        for (int a = 0; a < 4; a++) upk2(accA[a], dsP[a], dsPd[a]);

        float dfc = (qv[0]*dsP[0] + qv[1]*dsP[1] + qv[2]*dsP[2] + qv[3]*dsP[3]) * invM;
        float duP = (qv[0]*dsPd[0] + qv[1]*dsPd[1] + qv[2]*dsPd[2] + qv[3]*dsPd[3]) * invM;
        float dux = dsP[1] * invM * fc * q0;
        float duy = dsP[2] * invM * fc * q0;
        float duz = dsP[3] * invM * fc * q0;

        float du  = fc * duP;
        float drs = dfc * dfc_dr + du * du_dr;
        float dot = dux*ux + duy*uy + duz*uz;

        float fx = 0.0f, fy = 0.0f, fz = 0.0f;
        if (valid) {
            fx = drs*ux + (dux - dot*ux)*inv;
            fy = drs*uy + (duy - dot*uy)*inv;
            fz = drs*uz + (duz - dot*uz)*inv;
        }

        int nb = list_neigh[(long)bn * Mc + m];
        if (nb > 0) {
            long fj = ((long)b * NTOT + (nb - 1)) * 3;
            atomicAdd(&Force[fj + 0], -fx);
            atomicAdd(&Force[fj + 1], -fy);
            atomicAdd(&Force[fj + 2], -fz);
        }

        vals[0] += fx;   vals[1] += fy;   vals[2] += fz;
        vals[3]  += x*fx; vals[4]  += x*fy; vals[5]  += x*fz;
        vals[6]  += y*fx; vals[7]  += y*fy; vals[8]  += y*fz;
        vals[9]  += z*fx; vals[10] += z*fy; vals[11] += z*fz;
    }
    vals[12] = vals[13] = vals[14] = vals[15] = 0.0f;

    // 16-component packed butterfly + parity add (once per 2 neighbors)
    int lane = t & 31;
    bstep<8, 16>(vals, lane);
    bstep<4,  8>(vals, lane);
    bstep<2,  4>(vals, lane);
    bstep<1,  2>(vals, lane);
    vals[0] += __shfl_xor_sync(0xffffffffu, vals[0], 1);
    if ((lane & 1) == 0) {
        int c = (lane >> 1) & 15;
        if (c < 12) atomicAdd(&acc[c], vals[0]);
    }
    __syncthreads();
    if (t < 3)  atomicAdd(&Force[((long)b*NTOT + n)*3 + t], acc[t]);
    if (t >= 3 && t < 12) atomicAdd(&Virial[b*9 + (t - 3)], -acc[t]);
}

// ---------------- launch ---------------------------------------------------
extern "C" void kernel_launch(void* const* d_in, const int* in_sizes, int n_in,
                              void* d_out, int out_size) {
    const int*   list_neigh = (const int*)  d_in[0];
    const int*   tmap       = (const int*)  d_in[1];
    const float* rvec       = (const float*)d_in[2];
    const float* cparam     = (const float*)d_in[3];
    const float* W0         = (const float*)d_in[4];
    const float* b0         = (const float*)d_in[5];
    const float* W1         = (const float*)d_in[6];
    const float* b1         = (const float*)d_in[7];
    const float* W2         = (const float*)d_in[8];
    const float* b2         = (const float*)d_in[9];
    const float* Wout       = (const float*)d_in[10];
    const float* bout       = (const float*)d_in[11];

    float* out      = (float*)d_out;
    float* outEtot  = out + O_ETOT;
    float* outEi    = out + O_EI;
    float* outForce = out + O_FORCE;
    float* outVir   = out + O_VIR;

    prep_kernel<<<(OUT_TOTAL + 255) / 256, 256>>>(out, W0, W1, W2);
    feat_kernel<<<Bc*Nc, 128>>>(rvec, tmap, cparam);
    stats_kernel<<<1, 256>>>(tmap);
    mlp_kernel<<<Bc*Nc / (MLP_WARPS*APW), 128>>>(tmap, W0, b0, W1, b1, W2, b2,
                                                 Wout, bout, outEi, outEtot);
    grad_kernel<<<Bc*Nc, 128>>>(rvec, tmap, cparam, list_neigh, outForce, outVir);
}